// round 4
// baseline (speedup 1.0000x reference)
#include <cuda_runtime.h>
#include <mma.h>
#include <math.h>

using namespace nvcuda;

#define B_    4
#define S_    4096
#define D_    1024
#define H_    16
#define DH_   64
#define NF_   2049
#define NFFT  4096
#define LOGN  12

// ---------------- scratch (device globals; no allocations allowed) ----------------
__device__ float  g_Vt[(size_t)B_ * D_ * S_];   // V transposed: [b][c=h*64+d][s]
__device__ float  g_At[(size_t)B_ * D_ * S_];   // attn transposed, same layout
__device__ float2 g_tw[NFFT / 2];               // e^{-2*pi*i*k/N}
__device__ float  g_xpart[B_ * 32 * D_];        // partial sums of x over s-chunks
__device__ float  g_xsum[B_ * D_];              // sum of x over s
__device__ float  g_meanq[B_ * D_];             // mean_q [b][h*64+dh]
__device__ float  g_hdn[B_ * D_];               // gelu(mlp1)
__device__ float  g_gri[B_ * 2 * NF_];          // gates real|imag

// ---------------- twiddle table ----------------
__global__ void __launch_bounds__(256) k_twiddle() {
    int i = blockIdx.x * blockDim.x + threadIdx.x;
    if (i < NFFT / 2) {
        double ang = -6.283185307179586476925286766559 * (double)i / (double)NFFT;
        g_tw[i] = make_float2((float)cos(ang), (float)sin(ang));
    }
}

// ---------------- gate path (tiny) ----------------
__global__ void __launch_bounds__(128) k_xpart(const float* __restrict__ x) {
    int d = blockIdx.x * 128 + threadIdx.x;
    int chunk = blockIdx.y;          // 0..31
    int b = blockIdx.z;
    const float* p = x + ((size_t)b * S_ + (size_t)chunk * 128) * D_ + d;
    float acc = 0.f;
    #pragma unroll 4
    for (int s = 0; s < 128; s++) acc += p[(size_t)s * D_];
    g_xpart[(b * 32 + chunk) * D_ + d] = acc;
}

__global__ void __launch_bounds__(128) k_xsum() {
    int d = blockIdx.x * 128 + threadIdx.x;
    int b = blockIdx.y;
    float acc = 0.f;
    #pragma unroll
    for (int q = 0; q < 32; q++) acc += g_xpart[(b * 32 + q) * D_ + d];
    g_xsum[b * D_ + d] = acc;
}

__global__ void __launch_bounds__(128) k_meanq(const float* __restrict__ Wq) {
    int c = blockIdx.x * 128 + threadIdx.x;
    int b = blockIdx.y;
    const float* w  = Wq + (size_t)c * D_;
    const float* xm = g_xsum + b * D_;
    float acc = 0.f;
    for (int d = 0; d < D_; d++) acc += xm[d] * w[d];
    g_meanq[b * D_ + c] = acc * (1.0f / S_);
}

// layernorm per (b,h) over DH, mean over h, then mlp1+gelu. one block per b.
// 256 threads; each thread owns 4 of the 1024 channels/outputs.
__global__ void __launch_bounds__(256) k_lnmlp1(const float* __restrict__ gamma,
                                                const float* __restrict__ beta,
                                                const float* __restrict__ w1,
                                                const float* __restrict__ b1) {
    __shared__ float sv[16][64];
    __shared__ float sq[64];
    __shared__ float smean[16], srstd[16];
    int b = blockIdx.x;
    int t = threadIdx.x;           // 0..255

    #pragma unroll
    for (int r = 0; r < 4; r++) {
        int c = t + r * 256;       // 0..1023
        sv[c >> 6][c & 63] = g_meanq[b * D_ + c];
    }
    __syncthreads();
    if (t < 16) {
        float m = 0.f;
        for (int q = 0; q < 64; q++) m += sv[t][q];
        m *= (1.f / 64.f);
        float var = 0.f;
        for (int q = 0; q < 64; q++) { float dd = sv[t][q] - m; var += dd * dd; }
        var *= (1.f / 64.f);
        smean[t] = m;
        srstd[t] = rsqrtf(var + 1e-5f);
    }
    __syncthreads();
    #pragma unroll
    for (int r = 0; r < 4; r++) {
        int c = t + r * 256;
        int h = c >> 6, j = c & 63;
        sv[h][j] = (sv[h][j] - smean[h]) * srstd[h] * gamma[j] + beta[j];
    }
    __syncthreads();
    if (t < 64) {
        float m = 0.f;
        for (int q = 0; q < 16; q++) m += sv[q][t];
        sq[t] = m * (1.f / 16.f);
    }
    __syncthreads();
    // mlp1: hdn[b][c] = gelu( sum_j sq[j]*w1[c][j] + b1[c] ), exact gelu (erf)
    #pragma unroll
    for (int r = 0; r < 4; r++) {
        int c = t + r * 256;
        float acc = b1[c];
        const float* wr = w1 + (size_t)c * 64;
        #pragma unroll 8
        for (int q = 0; q < 64; q++) acc += sq[q] * wr[q];
        g_hdn[b * D_ + c] = 0.5f * acc * (1.f + erff(acc * 0.70710678118654752f));
    }
}

__global__ void __launch_bounds__(128) k_mlp2(const float* __restrict__ w2,
                                              const float* __restrict__ b2) {
    int warp = threadIdx.x >> 5, lane = threadIdx.x & 31;
    int r = blockIdx.x * 4 + warp;
    int b = blockIdx.y;
    if (r >= 2 * NF_) return;
    const float* hd = g_hdn + b * D_;
    const float* w  = w2 + (size_t)r * D_;
    float acc = 0.f;
    for (int i = lane; i < D_; i += 32) acc += hd[i] * w[i];
    #pragma unroll
    for (int o = 16; o; o >>= 1) acc += __shfl_xor_sync(0xffffffffu, acc, o);
    if (lane == 0) g_gri[b * 2 * NF_ + r] = acc + b2[r];
}

// ---------------- TF32 WMMA GEMM: C[m,n] = sum_k A[m,k] * W[n,k] ----------------
// M=16384 (b*4096+s), N=1024, K=1024.
// ACOL:   A stored column-major per-batch (g_At layout [b][k][m_s]); else row-major.
// TSTORE: store C transposed to [b][n][s] (for g_Vt); else row-major to C.
template <bool ACOL, bool TSTORE>
__global__ void __launch_bounds__(256) k_gemm(const float* __restrict__ A,
                                              const float* __restrict__ W,
                                              float* __restrict__ C) {
    extern __shared__ float sm[];
    constexpr int ASZ = ACOL ? 32 * 132 : 128 * 36;
    float* As = sm;
    float* Bs = sm + ASZ;

    const int tid = threadIdx.x;
    const int warp = tid >> 5;
    const int wm = warp & 3;   // 4 warps along M
    const int wn = warp >> 2;  // 2 warps along N
    const int n0 = blockIdx.x * 128;
    const int m0 = blockIdx.y * 128;

    const float* Abase;
    if (ACOL) {
        int b  = m0 >> 12;
        int s0 = m0 & 4095;
        Abase = A + (size_t)b * ((size_t)D_ * S_) + s0;
    } else {
        Abase = A + (size_t)m0 * D_;
    }

    wmma::fragment<wmma::accumulator, 16, 16, 8, float> acc[2][4];
    #pragma unroll
    for (int i = 0; i < 2; i++)
        #pragma unroll
        for (int j = 0; j < 4; j++) wmma::fill_fragment(acc[i][j], 0.0f);

    for (int k0 = 0; k0 < 1024; k0 += 32) {
        if (ACOL) {
            #pragma unroll
            for (int t = 0; t < 4; t++) {
                int idx = tid + t * 256;
                int col = idx >> 5;           // k within tile 0..31
                int mm  = (idx & 31) * 4;     // m within tile, step 4
                float4 v = *(const float4*)(Abase + (size_t)(k0 + col) * S_ + mm);
                *(float4*)(As + col * 132 + mm) = v;
            }
        } else {
            #pragma unroll
            for (int t = 0; t < 4; t++) {
                int idx = tid + t * 256;
                int row = idx >> 3;
                int c4  = (idx & 7) * 4;
                float4 v = *(const float4*)(Abase + (size_t)row * D_ + k0 + c4);
                *(float4*)(As + row * 36 + c4) = v;
            }
        }
        #pragma unroll
        for (int t = 0; t < 4; t++) {
            int idx = tid + t * 256;
            int row = idx >> 3;
            int c4  = (idx & 7) * 4;
            float4 v = *(const float4*)(W + (size_t)(n0 + row) * D_ + k0 + c4);
            *(float4*)(Bs + row * 36 + c4) = v;
        }
        __syncthreads();

        #pragma unroll
        for (int kk = 0; kk < 32; kk += 8) {
            wmma::fragment<wmma::matrix_b, 16, 16, 8, wmma::precision::tf32, wmma::col_major> bF[4];
            #pragma unroll
            for (int j = 0; j < 4; j++) {
                wmma::load_matrix_sync(bF[j], Bs + (wn * 64 + j * 16) * 36 + kk, 36);
                #pragma unroll
                for (int e = 0; e < bF[j].num_elements; e++)
                    bF[j].x[e] = wmma::__float_to_tf32(bF[j].x[e]);
            }
            if (ACOL) {
                wmma::fragment<wmma::matrix_a, 16, 16, 8, wmma::precision::tf32, wmma::col_major> aF[2];
                #pragma unroll
                for (int i = 0; i < 2; i++) {
                    wmma::load_matrix_sync(aF[i], As + kk * 132 + wm * 32 + i * 16, 132);
                    #pragma unroll
                    for (int e = 0; e < aF[i].num_elements; e++)
                        aF[i].x[e] = wmma::__float_to_tf32(aF[i].x[e]);
                }
                #pragma unroll
                for (int i = 0; i < 2; i++)
                    #pragma unroll
                    for (int j = 0; j < 4; j++)
                        wmma::mma_sync(acc[i][j], aF[i], bF[j], acc[i][j]);
            } else {
                wmma::fragment<wmma::matrix_a, 16, 16, 8, wmma::precision::tf32, wmma::row_major> aF[2];
                #pragma unroll
                for (int i = 0; i < 2; i++) {
                    wmma::load_matrix_sync(aF[i], As + (wm * 32 + i * 16) * 36 + kk, 36);
                    #pragma unroll
                    for (int e = 0; e < aF[i].num_elements; e++)
                        aF[i].x[e] = wmma::__float_to_tf32(aF[i].x[e]);
                }
                #pragma unroll
                for (int i = 0; i < 2; i++)
                    #pragma unroll
                    for (int j = 0; j < 4; j++)
                        wmma::mma_sync(acc[i][j], aF[i], bF[j], acc[i][j]);
            }
        }
        __syncthreads();
    }

    if (TSTORE) {
        // write C^T through smem: Ct[n][m], ld=132 (aliases As/Bs region)
        float* Ct = sm;
        #pragma unroll
        for (int i = 0; i < 2; i++)
            #pragma unroll
            for (int j = 0; j < 4; j++)
                wmma::store_matrix_sync(Ct + (wn * 64 + j * 16) * 132 + wm * 32 + i * 16,
                                        acc[i][j], 132, wmma::mem_col_major);
        __syncthreads();
        int b  = m0 >> 12;
        int s0 = m0 & 4095;
        #pragma unroll
        for (int t = 0; t < 16; t++) {
            int idx = tid + t * 256;
            int n  = idx >> 5;
            int mm = (idx & 31) * 4;
            float4 v = *(float4*)(Ct + n * 132 + mm);
            *(float4*)(C + ((size_t)(b * D_ + n0 + n)) * S_ + s0 + mm) = v;
        }
    } else {
        #pragma unroll
        for (int i = 0; i < 2; i++)
            #pragma unroll
            for (int j = 0; j < 4; j++)
                wmma::store_matrix_sync(C + (size_t)(m0 + wm * 32 + i * 16) * D_ + n0 + wn * 64 + j * 16,
                                        acc[i][j], D_, wmma::mem_row_major);
    }
}

// ---------------- fused FFT -> gate*modReLU -> iFFT ----------------
// One CTA per (b, h, channel-pair). z = V[2p] + i*V[2p+1]. 512 threads.
__global__ void __launch_bounds__(512) k_fft(const float* __restrict__ mbias) {
    extern __shared__ float2 sd[];
    float2* dat = sd;            // 4096 complex
    float2* tw  = sd + NFFT;     // 2048 complex

    const int tid = threadIdx.x;
    const int p = blockIdx.x;    // 0..31
    const int h = blockIdx.y;    // 0..15
    const int b = blockIdx.z;    // 0..3

    const float* va = g_Vt + ((size_t)((b * H_ + h) * DH_ + 2 * p)) * S_;
    const float* vb = va + S_;
    for (int i = tid; i < NFFT; i += 512) dat[i] = make_float2(va[i], vb[i]);
    for (int i = tid; i < NFFT / 2; i += 512) tw[i] = g_tw[i];
    __syncthreads();

    // forward radix-2 DIF (natural -> bit-reversed), twiddle e^{-}
    for (int ls = LOGN; ls >= 1; ls--) {
        int half = 1 << (ls - 1);
        int sh = ls - 1;
        #pragma unroll 4
        for (int q = tid; q < NFFT / 2; q += 512) {
            int j  = q & (half - 1);
            int i0 = ((q >> sh) << ls) | j;
            int i1 = i0 + half;
            float2 u = dat[i0], v = dat[i1];
            float2 w = tw[j << (LOGN - ls)];
            dat[i0] = make_float2(u.x + v.x, u.y + v.y);
            float dx = u.x - v.x, dy = u.y - v.y;
            dat[i1] = make_float2(dx * w.x - dy * w.y, dx * w.y + dy * w.x);
        }
        __syncthreads();
    }

    // spectral: separate Hermitian parts, ortho scale, gate, modReLU, repack
    const float bias = mbias[0];
    const float inv64 = 1.0f / 64.0f;   // 1/sqrt(N)
    const float* grb = g_gri + b * 2 * NF_;
    for (int k = tid; k <= NFFT / 2; k += 512) {
        float gr = grb[k];
        float gi = grb[NF_ + k];
        int p1 = (int)(__brev((unsigned)k) >> (32 - LOGN));
        if (k == 0 || k == NFFT / 2) {
            float2 Z = dat[p1];
            float Av = Z.x * inv64, Bv = Z.y * inv64;
            float ar = Av * gr, ai = Av * gi;
            float ma = sqrtf(ar * ar + ai * ai);
            float sa = fmaxf(ma + bias, 0.f) / fmaxf(ma, 1e-12f);
            float Aout = ar * sa * inv64;             // irfft drops imag of bins 0, N/2
            float br2 = Bv * gr, bi2 = Bv * gi;
            float mb = sqrtf(br2 * br2 + bi2 * bi2);
            float sb = fmaxf(mb + bias, 0.f) / fmaxf(mb, 1e-12f);
            float Bout = br2 * sb * inv64;
            dat[p1] = make_float2(Aout, Bout);
        } else {
            int p2 = (int)(__brev((unsigned)(NFFT - k)) >> (32 - LOGN));
            float2 Z1 = dat[p1], Z2 = dat[p2];
            float Ar = 0.5f * (Z1.x + Z2.x) * inv64;
            float Ai = 0.5f * (Z1.y - Z2.y) * inv64;
            float Br = 0.5f * (Z1.y + Z2.y) * inv64;
            float Bi = 0.5f * (Z2.x - Z1.x) * inv64;
            float zar = Ar * gr - Ai * gi, zai = Ar * gi + Ai * gr;
            float ma = sqrtf(zar * zar + zai * zai);
            float sa = fmaxf(ma + bias, 0.f) / fmaxf(ma, 1e-12f) * inv64;
            zar *= sa; zai *= sa;
            float zbr = Br * gr - Bi * gi, zbi = Br * gi + Bi * gr;
            float mb = sqrtf(zbr * zbr + zbi * zbi);
            float sb = fmaxf(mb + bias, 0.f) / fmaxf(mb, 1e-12f) * inv64;
            zbr *= sb; zbi *= sb;
            dat[p1] = make_float2(zar - zbi, zai + zbr);                 // Z'_k
            dat[p2] = make_float2(zar + zbi, zbr - zai);                 // Z'_{N-k}
        }
    }
    __syncthreads();

    // inverse radix-2 DIT (bit-reversed -> natural), twiddle e^{+} = conj(tw)
    for (int ls = 1; ls <= LOGN; ls++) {
        int half = 1 << (ls - 1);
        int sh = ls - 1;
        #pragma unroll 4
        for (int q = tid; q < NFFT / 2; q += 512) {
            int j  = q & (half - 1);
            int i0 = ((q >> sh) << ls) | j;
            int i1 = i0 + half;
            float2 w = tw[j << (LOGN - ls)];
            float2 u = dat[i0], v = dat[i1];
            float tr = v.x * w.x + v.y * w.y;
            float ti = v.y * w.x - v.x * w.y;
            dat[i0] = make_float2(u.x + tr, u.y + ti);
            dat[i1] = make_float2(u.x - tr, u.y - ti);
        }
        __syncthreads();
    }

    float* oa = g_At + ((size_t)((b * H_ + h) * DH_ + 2 * p)) * S_;
    float* ob = oa + S_;
    for (int i = tid; i < NFFT; i += 512) {
        float2 z = dat[i];
        oa[i] = z.x;
        ob[i] = z.y;
    }
}

// ---------------- launch ----------------
extern "C" void kernel_launch(void* const* d_in, const int* in_sizes, int n_in,
                              void* d_out, int out_size) {
    const float* x     = (const float*)d_in[0];
    const float* Wq    = (const float*)d_in[1];
    const float* Wv    = (const float*)d_in[2];
    const float* Wo    = (const float*)d_in[3];
    const float* gamma = (const float*)d_in[4];
    const float* beta  = (const float*)d_in[5];
    const float* w1    = (const float*)d_in[6];
    const float* b1    = (const float*)d_in[7];
    const float* w2    = (const float*)d_in[8];
    const float* b2    = (const float*)d_in[9];
    const float* mbias = (const float*)d_in[10];
    float* out = (float*)d_out;

    float *vt = nullptr, *at = nullptr;
    cudaGetSymbolAddress((void**)&vt, g_Vt);
    cudaGetSymbolAddress((void**)&at, g_At);

    const int smem_gemm_v = (128 * 132) * 4;                 // 67584 (Ct region dominates)
    const int smem_gemm_o = (32 * 132 + 128 * 36) * 4;       // 35328
    const int smem_fft    = (NFFT + NFFT / 2) * 8;           // 49152

    cudaFuncSetAttribute(k_gemm<false, true>,  cudaFuncAttributeMaxDynamicSharedMemorySize, smem_gemm_v);
    cudaFuncSetAttribute(k_gemm<true,  false>, cudaFuncAttributeMaxDynamicSharedMemorySize, smem_gemm_o);
    cudaFuncSetAttribute(k_fft,                cudaFuncAttributeMaxDynamicSharedMemorySize, smem_fft);

    // gate path (tiny) + twiddles
    k_twiddle<<<8, 256>>>();
    k_xpart<<<dim3(8, 32, 4), 128>>>(x);
    k_xsum<<<dim3(8, 4), 128>>>();
    k_meanq<<<dim3(8, 4), 128>>>(Wq);
    k_lnmlp1<<<4, 256>>>(gamma, beta, w1, b1);
    k_mlp2<<<dim3((2 * NF_ + 3) / 4, 4), 128>>>(w2, b2);

    // V projection, transposed output [b][c][s]
    k_gemm<false, true><<<dim3(8, 128), 256, smem_gemm_v>>>(x, Wv, vt);

    // fused spectral mixer
    k_fft<<<dim3(32, 16, 4), 512, smem_fft>>>(mbias);

    // output projection from transposed attn layout
    k_gemm<true, false><<<dim3(8, 128), 256, smem_gemm_o>>>(at, Wo, out);
}